// round 1
// baseline (speedup 1.0000x reference)
#include <cuda_runtime.h>
#include <math.h>

#define D 256
#define MAXN 8192

// Scratch (allocation-free rule: __device__ globals)
__device__ float g_zn[MAXN * D];   // normalized rows, 8 MB
__device__ float g_S[MAXN];        // sum_{j!=i} exp(sim_ij - 2)
__device__ float g_pos[MAXN];      // sim[i, partner(i)]

// ---------------------------------------------------------------------------
// exp(x) for x in [-4, 0+eps] on the FMA pipe (avoids MUFU throughput wall).
// exp(x) = 2^(x*log2e); split t = i + f with f in [-0.5, 0.5] via rint,
// Taylor for 2^f (err ~1.2e-7), scale by 2^i through exponent bits (i in [-6,0]).
// ---------------------------------------------------------------------------
__device__ __forceinline__ float fast_exp_nonpos(float x) {
    float t  = x * 1.4426950408889634f;
    float fi = rintf(t);
    float f  = t - fi;
    float p  = 1.5403530394e-4f;
    p = fmaf(p, f, 1.3333558147e-3f);
    p = fmaf(p, f, 9.6181291071e-3f);
    p = fmaf(p, f, 5.5504108665e-2f);
    p = fmaf(p, f, 2.4022650696e-1f);
    p = fmaf(p, f, 6.9314718056e-1f);
    p = fmaf(p, f, 1.0f);
    int i = (int)fi;
    return p * __int_as_float((i + 127) << 23);
}

// ---------------------------------------------------------------------------
// Kernel 1: L2-normalize each row of z = concat(z_i, z_j); also zero S/pos.
// One block (256 threads) per row; D == 256 so one element per thread.
// ---------------------------------------------------------------------------
__global__ void k_normalize(const float* __restrict__ zi,
                            const float* __restrict__ zj, int B) {
    int row = blockIdx.x;
    const float* src = (row < B) ? (zi + (size_t)row * D)
                                 : (zj + (size_t)(row - B) * D);
    int t = threadIdx.x;
    float v = src[t];
    float s = v * v;
    #pragma unroll
    for (int o = 16; o > 0; o >>= 1) s += __shfl_xor_sync(0xffffffffu, s, o);
    __shared__ float ws[8];
    if ((t & 31) == 0) ws[t >> 5] = s;
    __syncthreads();
    if (t < 32) {
        float x = (t < 8) ? ws[t] : 0.0f;
        #pragma unroll
        for (int o = 4; o > 0; o >>= 1) x += __shfl_xor_sync(0xffffffffu, x, o);
        if (t == 0) ws[0] = x;
    }
    __syncthreads();
    float norm = fmaxf(sqrtf(ws[0]), 1e-8f);
    g_zn[(size_t)row * D + t] = v / norm;
    if (t == 0) { g_S[row] = 0.0f; g_pos[row] = 0.0f; }
}

// ---------------------------------------------------------------------------
// Kernel 2: fused sim-tile GEMM + exp row-sum epilogue.
// 128x128 output tile per block, BK=32, 256 threads, 8x8 microtile/thread.
// sim = 2 * (zn_r . zn_c); accumulate exp(sim-2) into g_S[r] for c != r;
// record g_pos[r] when c is the partner column.
// ---------------------------------------------------------------------------
#define BM 128
#define BN 128
#define BK 32

__global__ __launch_bounds__(256)
void k_simgemm(int Nn, int B) {
    const int r0 = blockIdx.y * BM;
    const int c0 = blockIdx.x * BN;

    __shared__ float As[BK][BM + 4];
    __shared__ float Bs[BK][BN + 4];
    __shared__ float rowS[BM];

    const int tid = threadIdx.x;
    const int tx  = tid & 15;    // 0..15 -> 8 cols each
    const int ty  = tid >> 4;    // 0..15 -> 8 rows each

    if (tid < BM) rowS[tid] = 0.0f;

    float acc[8][8];
    #pragma unroll
    for (int i = 0; i < 8; i++)
        #pragma unroll
        for (int j = 0; j < 8; j++) acc[i][j] = 0.0f;

    for (int kk = 0; kk < D; kk += BK) {
        // cooperative load: 128 rows x 32 k each for A and B (float4 along k)
        #pragma unroll
        for (int q = 0; q < 4; q++) {
            int li  = tid + q * 256;       // 0..1023
            int row = li >> 3;             // 0..127
            int k4  = (li & 7) << 2;       // 0,4,...,28
            float4 va = *reinterpret_cast<const float4*>(
                &g_zn[(size_t)(r0 + row) * D + kk + k4]);
            As[k4 + 0][row] = va.x; As[k4 + 1][row] = va.y;
            As[k4 + 2][row] = va.z; As[k4 + 3][row] = va.w;
            float4 vb = *reinterpret_cast<const float4*>(
                &g_zn[(size_t)(c0 + row) * D + kk + k4]);
            Bs[k4 + 0][row] = vb.x; Bs[k4 + 1][row] = vb.y;
            Bs[k4 + 2][row] = vb.z; Bs[k4 + 3][row] = vb.w;
        }
        __syncthreads();

        #pragma unroll
        for (int k = 0; k < BK; k++) {
            float ra[8], rb[8];
            #pragma unroll
            for (int i = 0; i < 8; i++) ra[i] = As[k][ty * 8 + i];
            #pragma unroll
            for (int j = 0; j < 8; j++) rb[j] = Bs[k][tx * 8 + j];
            #pragma unroll
            for (int i = 0; i < 8; i++)
                #pragma unroll
                for (int j = 0; j < 8; j++)
                    acc[i][j] = fmaf(ra[i], rb[j], acc[i][j]);
        }
        __syncthreads();
    }

    // Epilogue: exp + row-sum, skip diagonal, capture positive pair.
    float rs[8];
    #pragma unroll
    for (int i = 0; i < 8; i++) rs[i] = 0.0f;

    #pragma unroll
    for (int i = 0; i < 8; i++) {
        int r = r0 + ty * 8 + i;
        int partner = (r < B) ? (r + B) : (r - B);
        #pragma unroll
        for (int j = 0; j < 8; j++) {
            int c = c0 + tx * 8 + j;
            float sim = 2.0f * acc[i][j];   // cos / temperature(0.5)
            if (c != r) rs[i] += fast_exp_nonpos(sim - 2.0f);
            if (c == partner) g_pos[r] = sim;   // unique writer
        }
    }

    #pragma unroll
    for (int i = 0; i < 8; i++)
        atomicAdd(&rowS[ty * 8 + i], rs[i]);
    __syncthreads();
    if (tid < BM) atomicAdd(&g_S[r0 + tid], rowS[tid]);
}

// ---------------------------------------------------------------------------
// Kernel 3: loss = (1/N) * sum_i (2 + log(S_i) - pos_i)
// ---------------------------------------------------------------------------
__global__ void k_final(float* __restrict__ out, int Nn) {
    int t = threadIdx.x;   // 1024 threads, single block
    float s = 0.0f;
    for (int i = t; i < Nn; i += 1024)
        s += 2.0f + logf(g_S[i]) - g_pos[i];
    #pragma unroll
    for (int o = 16; o > 0; o >>= 1) s += __shfl_xor_sync(0xffffffffu, s, o);
    __shared__ float ws[32];
    if ((t & 31) == 0) ws[t >> 5] = s;
    __syncthreads();
    if (t < 32) {
        float x = ws[t];
        #pragma unroll
        for (int o = 16; o > 0; o >>= 1) x += __shfl_xor_sync(0xffffffffu, x, o);
        if (t == 0) out[0] = x / (float)Nn;
    }
}

// ---------------------------------------------------------------------------
extern "C" void kernel_launch(void* const* d_in, const int* in_sizes, int n_in,
                              void* d_out, int out_size) {
    const float* zi = (const float*)d_in[0];
    const float* zj = (const float*)d_in[1];
    int B  = in_sizes[0] / D;    // 4096
    int Nn = 2 * B;              // 8192

    k_normalize<<<Nn, 256>>>(zi, zj, B);
    dim3 grid(Nn / BN, Nn / BM); // 64 x 64 tiles
    k_simgemm<<<grid, 256>>>(Nn, B);
    k_final<<<1, 1024>>>((float*)d_out, Nn);
}

// round 4
// speedup vs baseline: 4.9577x; 4.9577x over previous
#include <cuda_runtime.h>
#include <cuda_bf16.h>
#include <cstdint>
#include <math.h>

#define D 256
#define MAXN 8192
#define TILE 128
#define STRIDE 264   // bf16 elems per smem row: 528B = 132 words -> conflict-free ldmatrix

// Scratch (__device__ globals: allocation-free rule)
__device__ __nv_bfloat16 g_znb[MAXN * D];   // normalized rows, bf16 (4 MB)
__device__ float g_S[MAXN];                 // sum_{j!=i} exp(sim_ij - 2)
__device__ float g_pos[MAXN];               // sim[i, partner(i)]

__device__ __forceinline__ uint32_t smem_u32(const void* p) {
    uint32_t a;
    asm("{ .reg .u64 t; cvta.to.shared.u64 t, %1; cvt.u32.u64 %0, t; }"
        : "=r"(a) : "l"(p));
    return a;
}

// ---------------------------------------------------------------------------
// exp(x), x in ~[-4, 0+eps], FMA-pipe polynomial (avoids MUFU wall)
// ---------------------------------------------------------------------------
__device__ __forceinline__ float fast_exp_nonpos(float x) {
    float t  = x * 1.4426950408889634f;
    float fi = rintf(t);
    float f  = t - fi;
    float p  = 1.5403530394e-4f;
    p = fmaf(p, f, 1.3333558147e-3f);
    p = fmaf(p, f, 9.6181291071e-3f);
    p = fmaf(p, f, 5.5504108665e-2f);
    p = fmaf(p, f, 2.4022650696e-1f);
    p = fmaf(p, f, 6.9314718056e-1f);
    p = fmaf(p, f, 1.0f);
    int i = (int)fi;
    return p * __int_as_float((i + 127) << 23);
}

// ---------------------------------------------------------------------------
// Kernel 1: normalize rows of concat(z_i, z_j) -> bf16; zero S/pos.
// ---------------------------------------------------------------------------
__global__ void k_normalize(const float* __restrict__ zi,
                            const float* __restrict__ zj, int B) {
    int row = blockIdx.x;
    const float* src = (row < B) ? (zi + (size_t)row * D)
                                 : (zj + (size_t)(row - B) * D);
    int t = threadIdx.x;
    float v = src[t];
    float s = v * v;
    #pragma unroll
    for (int o = 16; o > 0; o >>= 1) s += __shfl_xor_sync(0xffffffffu, s, o);
    __shared__ float ws[8];
    if ((t & 31) == 0) ws[t >> 5] = s;
    __syncthreads();
    if (t < 32) {
        float x = (t < 8) ? ws[t] : 0.0f;
        #pragma unroll
        for (int o = 4; o > 0; o >>= 1) x += __shfl_xor_sync(0xffffffffu, x, o);
        if (t == 0) ws[0] = x;
    }
    __syncthreads();
    float norm = fmaxf(sqrtf(ws[0]), 1e-8f);
    g_znb[(size_t)row * D + t] = __float2bfloat16(v / norm);
    if (t == 0) { g_S[row] = 0.0f; g_pos[row] = 0.0f; }
}

// ---------------------------------------------------------------------------
// Kernel 2: 128x128 tile via mma.sync.m16n8k16 bf16 + fused exp-rowsum.
// Full K=256 resident in SMEM (A,B tiles 128x264 bf16 each).
// 8 warps: warp_m = wid&3 (32 rows each), warp_n = wid>>2 (64 cols each).
// ---------------------------------------------------------------------------
__global__ __launch_bounds__(256)
void k_simgemm_mma(int Nn, int B) {
    extern __shared__ __nv_bfloat16 smem[];
    __nv_bfloat16* As = smem;                    // [128][STRIDE]
    __nv_bfloat16* Bs = smem + TILE * STRIDE;    // [128][STRIDE]

    const int tid = threadIdx.x;
    const int wid = tid >> 5, lid = tid & 31;
    const int r0 = blockIdx.y * TILE, c0 = blockIdx.x * TILE;

    // cooperative load: 128 rows x 256 bf16 per matrix, uint4 (8 bf16) granules
    #pragma unroll
    for (int q = 0; q < 16; q++) {
        int li  = tid + q * 256;            // 0..4095
        int row = li >> 5;                  // 0..127
        int k   = (li & 31) << 3;           // 0..248
        *reinterpret_cast<uint4*>(&As[row * STRIDE + k]) =
            *reinterpret_cast<const uint4*>(&g_znb[(size_t)(r0 + row) * D + k]);
        *reinterpret_cast<uint4*>(&Bs[row * STRIDE + k]) =
            *reinterpret_cast<const uint4*>(&g_znb[(size_t)(c0 + row) * D + k]);
    }
    __syncthreads();

    const int warp_m = wid & 3;
    const int warp_n = wid >> 2;

    // per-lane ldmatrix addresses
    // A x4 at (m0, k0): lane L -> row m0+(L&15), col k0 + ((L>>4)<<3)
    uint32_t aAddr[2];
    #pragma unroll
    for (int mf = 0; mf < 2; mf++) {
        int row = warp_m * 32 + mf * 16 + (lid & 15);
        int col = (lid >> 4) << 3;
        aAddr[mf] = smem_u32(&As[row * STRIDE + col]);
    }
    // B x4 at (n0, k0): lane L -> row n0+((L>>4)<<3)+(L&7), col k0 + (L&8)
    uint32_t bAddr[4];
    #pragma unroll
    for (int nq = 0; nq < 4; nq++) {
        int row = warp_n * 64 + nq * 16 + ((lid >> 4) << 3) + (lid & 7);
        int col = (lid & 8);
        bAddr[nq] = smem_u32(&Bs[row * STRIDE + col]);
    }

    float acc[2][8][4];
    #pragma unroll
    for (int i = 0; i < 2; i++)
        #pragma unroll
        for (int j = 0; j < 8; j++)
            #pragma unroll
            for (int e = 0; e < 4; e++) acc[i][j][e] = 0.0f;

    #pragma unroll
    for (int ks = 0; ks < 16; ks++) {
        const uint32_t kb = ks * 16 * 2;   // byte offset along k
        uint32_t a[2][4], b[4][4];
        #pragma unroll
        for (int mf = 0; mf < 2; mf++)
            asm volatile("ldmatrix.sync.aligned.m8n8.x4.shared.b16 {%0,%1,%2,%3}, [%4];"
                         : "=r"(a[mf][0]), "=r"(a[mf][1]), "=r"(a[mf][2]), "=r"(a[mf][3])
                         : "r"(aAddr[mf] + kb));
        #pragma unroll
        for (int nq = 0; nq < 4; nq++)
            asm volatile("ldmatrix.sync.aligned.m8n8.x4.shared.b16 {%0,%1,%2,%3}, [%4];"
                         : "=r"(b[nq][0]), "=r"(b[nq][1]), "=r"(b[nq][2]), "=r"(b[nq][3])
                         : "r"(bAddr[nq] + kb));
        #pragma unroll
        for (int mf = 0; mf < 2; mf++)
            #pragma unroll
            for (int nf = 0; nf < 8; nf++) {
                const int nq = nf >> 1, base = (nf & 1) * 2;
                asm volatile(
                    "mma.sync.aligned.m16n8k16.row.col.f32.bf16.bf16.f32 "
                    "{%0,%1,%2,%3}, {%4,%5,%6,%7}, {%8,%9}, {%0,%1,%2,%3};"
                    : "+f"(acc[mf][nf][0]), "+f"(acc[mf][nf][1]),
                      "+f"(acc[mf][nf][2]), "+f"(acc[mf][nf][3])
                    : "r"(a[mf][0]), "r"(a[mf][1]), "r"(a[mf][2]), "r"(a[mf][3]),
                      "r"(b[nq][base]), "r"(b[nq][base + 1]));
            }
    }

    // Epilogue: sim = 2*acc; rowsum of exp(sim-2) excluding diagonal; capture pos.
    const int qrow = lid >> 2, qcol = lid & 3;
    #pragma unroll
    for (int mf = 0; mf < 2; mf++) {
        #pragma unroll
        for (int sub = 0; sub < 2; sub++) {
            const int r = r0 + warp_m * 32 + mf * 16 + sub * 8 + qrow;
            const int partner = (r < B) ? (r + B) : (r - B);
            float rs = 0.0f;
            #pragma unroll
            for (int nf = 0; nf < 8; nf++) {
                #pragma unroll
                for (int e = 0; e < 2; e++) {
                    const int c = c0 + warp_n * 64 + nf * 8 + qcol * 2 + e;
                    const float sim = 2.0f * acc[mf][nf][sub * 2 + e];
                    if (c != r) rs += fast_exp_nonpos(sim - 2.0f);
                    if (c == partner) g_pos[r] = sim;   // unique writer
                }
            }
            rs += __shfl_xor_sync(0xffffffffu, rs, 1);
            rs += __shfl_xor_sync(0xffffffffu, rs, 2);
            if (qcol == 0) atomicAdd(&g_S[r], rs);
        }
    }
}

// ---------------------------------------------------------------------------
// Kernel 3: loss = (1/N) * sum_i (2 + log(S_i) - pos_i)
// ---------------------------------------------------------------------------
__global__ void k_final(float* __restrict__ out, int Nn) {
    int t = threadIdx.x;
    float s = 0.0f;
    for (int i = t; i < Nn; i += 1024)
        s += 2.0f + logf(g_S[i]) - g_pos[i];
    #pragma unroll
    for (int o = 16; o > 0; o >>= 1) s += __shfl_xor_sync(0xffffffffu, s, o);
    __shared__ float ws[32];
    if ((t & 31) == 0) ws[t >> 5] = s;
    __syncthreads();
    if (t < 32) {
        float x = ws[t];
        #pragma unroll
        for (int o = 16; o > 0; o >>= 1) x += __shfl_xor_sync(0xffffffffu, x, o);
        if (t == 0) out[0] = x / (float)Nn;
    }
}

// ---------------------------------------------------------------------------
extern "C" void kernel_launch(void* const* d_in, const int* in_sizes, int n_in,
                              void* d_out, int out_size) {
    const float* zi = (const float*)d_in[0];
    const float* zj = (const float*)d_in[1];
    int B  = in_sizes[0] / D;   // 4096
    int Nn = 2 * B;             // 8192

    const int smem_bytes = 2 * TILE * STRIDE * sizeof(__nv_bfloat16);  // 135168
    cudaFuncSetAttribute(k_simgemm_mma,
                         cudaFuncAttributeMaxDynamicSharedMemorySize, smem_bytes);

    k_normalize<<<Nn, 256>>>(zi, zj, B);
    dim3 grid(Nn / TILE, Nn / TILE);   // 64 x 64
    k_simgemm_mma<<<grid, 256, smem_bytes>>>(Nn, B);
    k_final<<<1, 1024>>>((float*)d_out, Nn);
}

// round 7
// speedup vs baseline: 7.4543x; 1.5036x over previous
#include <cuda_runtime.h>
#include <cuda_bf16.h>
#include <cstdint>
#include <math.h>

#define D 256
#define MAXN 8192
#define TILE 128
#define CHK 136                      // bf16 elems per smem row: 272B = 17*16 (cp.async-aligned),
                                     // 68 words -> 4-bank row skew, conflict-free ldmatrix
#define CH_ELEMS (TILE * CHK)        // one 128x128 K-chunk (+pad) = 17408 elems
#define CH_BYTES (CH_ELEMS * 2)      // 34816 B

// Scratch (__device__ globals: allocation-free rule)
__device__ __nv_bfloat16 g_znb[MAXN * D];   // normalized rows, bf16 (4 MB)
__device__ float g_S[MAXN];                 // sum_{j!=i} exp(sim_ij - 2)
__device__ float g_pos[MAXN];               // sim[i, partner(i)]

__device__ __forceinline__ uint32_t smem_u32(const void* p) {
    uint32_t a;
    asm("{ .reg .u64 t; cvta.to.shared.u64 t, %1; cvt.u32.u64 %0, t; }"
        : "=r"(a) : "l"(p));
    return a;
}

__device__ __forceinline__ void cp_async16(uint32_t dst, const void* src) {
    asm volatile("cp.async.cg.shared.global [%0], [%1], 16;" :: "r"(dst), "l"(src));
}
#define CP_COMMIT() asm volatile("cp.async.commit_group;" ::: "memory")
#define CP_WAIT(n)  asm volatile("cp.async.wait_group %0;" :: "n"(n) : "memory")

// ---------------------------------------------------------------------------
// exp(x), x in ~[-4, 0+eps], FMA-pipe polynomial (avoids MUFU wall)
// ---------------------------------------------------------------------------
__device__ __forceinline__ float fast_exp_nonpos(float x) {
    float t  = x * 1.4426950408889634f;
    float fi = rintf(t);
    float f  = t - fi;
    float p  = 1.5403530394e-4f;
    p = fmaf(p, f, 1.3333558147e-3f);
    p = fmaf(p, f, 9.6181291071e-3f);
    p = fmaf(p, f, 5.5504108665e-2f);
    p = fmaf(p, f, 2.4022650696e-1f);
    p = fmaf(p, f, 6.9314718056e-1f);
    p = fmaf(p, f, 1.0f);
    int i = (int)fi;
    return p * __int_as_float((i + 127) << 23);
}

// ---------------------------------------------------------------------------
// Kernel 1: normalize rows of concat(z_i, z_j) -> bf16; zero S/pos.
// ---------------------------------------------------------------------------
__global__ void k_normalize(const float* __restrict__ zi,
                            const float* __restrict__ zj, int B) {
    int row = blockIdx.x;
    const float* src = (row < B) ? (zi + (size_t)row * D)
                                 : (zj + (size_t)(row - B) * D);
    int t = threadIdx.x;
    float v = src[t];
    float s = v * v;
    #pragma unroll
    for (int o = 16; o > 0; o >>= 1) s += __shfl_xor_sync(0xffffffffu, s, o);
    __shared__ float ws[8];
    if ((t & 31) == 0) ws[t >> 5] = s;
    __syncthreads();
    if (t < 32) {
        float x = (t < 8) ? ws[t] : 0.0f;
        #pragma unroll
        for (int o = 4; o > 0; o >>= 1) x += __shfl_xor_sync(0xffffffffu, x, o);
        if (t == 0) ws[0] = x;
    }
    __syncthreads();
    float norm = fmaxf(sqrtf(ws[0]), 1e-8f);
    g_znb[(size_t)row * D + t] = __float2bfloat16(v / norm);
    if (t == 0) { g_S[row] = 0.0f; g_pos[row] = 0.0f; }
}

// ---------------------------------------------------------------------------
// Kernel 2: lower-triangle 128x128 tiles (2080 CTAs), bf16 mma.sync,
// cp.async 2-chunk K pipeline, fused exp epilogue with dual row/col sums.
// SMEM: A[chunk0], A[chunk1], B[chunk0], B[chunk1], each 128x136 bf16.
// ---------------------------------------------------------------------------
__global__ __launch_bounds__(256)
void k_simgemm_sym(int Nn, int B) {
    extern __shared__ __nv_bfloat16 smem[];
    __nv_bfloat16* As = smem;                     // 2 chunks
    __nv_bfloat16* Bs = smem + 2 * CH_ELEMS;      // 2 chunks

    // decode lower-triangle tile (by >= bx)
    int idx = blockIdx.x;
    int by = (int)((sqrtf(8.0f * (float)idx + 1.0f) - 1.0f) * 0.5f);
    while ((by + 1) * (by + 2) / 2 <= idx) by++;
    while (by * (by + 1) / 2 > idx) by--;
    int bx = idx - by * (by + 1) / 2;
    const int r0 = by * TILE, c0 = bx * TILE;
    const bool diag = (by == bx);

    const int tid = threadIdx.x;
    const int wid = tid >> 5, lid = tid & 31;

    // issue both K-chunks as cp.async groups (chunk1 overlaps chunk0's MMA)
    #pragma unroll
    for (int c = 0; c < 2; c++) {
        #pragma unroll
        for (int q = 0; q < 8; q++) {
            int li  = tid + q * 256;            // 0..2047
            int row = li >> 4;                  // 0..127
            int kq  = (li & 15) << 3;           // 0..120
            uint32_t dstA = smem_u32(&As[c * CH_ELEMS + row * CHK + kq]);
            uint32_t dstB = smem_u32(&Bs[c * CH_ELEMS + row * CHK + kq]);
            cp_async16(dstA, &g_znb[(size_t)(r0 + row) * D + c * 128 + kq]);
            cp_async16(dstB, &g_znb[(size_t)(c0 + row) * D + c * 128 + kq]);
        }
        CP_COMMIT();
    }

    const int warp_m = wid & 3;
    const int warp_n = wid >> 2;

    // per-lane ldmatrix base addresses (chunk 0)
    uint32_t aAddr[2];
    #pragma unroll
    for (int mf = 0; mf < 2; mf++) {
        int row = warp_m * 32 + mf * 16 + (lid & 15);
        int col = (lid >> 4) << 3;
        aAddr[mf] = smem_u32(&As[row * CHK + col]);
    }
    uint32_t bAddr[4];
    #pragma unroll
    for (int nq = 0; nq < 4; nq++) {
        int row = warp_n * 64 + nq * 16 + ((lid >> 4) << 3) + (lid & 7);
        int col = (lid & 8);
        bAddr[nq] = smem_u32(&Bs[row * CHK + col]);
    }

    float acc[2][8][4];
    #pragma unroll
    for (int i = 0; i < 2; i++)
        #pragma unroll
        for (int j = 0; j < 8; j++)
            #pragma unroll
            for (int e = 0; e < 4; e++) acc[i][j][e] = 0.0f;

    #pragma unroll
    for (int ch = 0; ch < 2; ch++) {
        if (ch == 0) CP_WAIT(1); else CP_WAIT(0);
        __syncthreads();
        const uint32_t cb = ch * CH_BYTES;
        #pragma unroll
        for (int ks = 0; ks < 8; ks++) {
            const uint32_t kb = cb + ks * 32;   // byte offset along k
            uint32_t a[2][4], b[4][4];
            #pragma unroll
            for (int mf = 0; mf < 2; mf++)
                asm volatile("ldmatrix.sync.aligned.m8n8.x4.shared.b16 {%0,%1,%2,%3}, [%4];"
                             : "=r"(a[mf][0]), "=r"(a[mf][1]), "=r"(a[mf][2]), "=r"(a[mf][3])
                             : "r"(aAddr[mf] + kb));
            #pragma unroll
            for (int nq = 0; nq < 4; nq++)
                asm volatile("ldmatrix.sync.aligned.m8n8.x4.shared.b16 {%0,%1,%2,%3}, [%4];"
                             : "=r"(b[nq][0]), "=r"(b[nq][1]), "=r"(b[nq][2]), "=r"(b[nq][3])
                             : "r"(bAddr[nq] + kb));
            #pragma unroll
            for (int mf = 0; mf < 2; mf++)
                #pragma unroll
                for (int nf = 0; nf < 8; nf++) {
                    const int nq = nf >> 1, base = (nf & 1) * 2;
                    asm volatile(
                        "mma.sync.aligned.m16n8k16.row.col.f32.bf16.bf16.f32 "
                        "{%0,%1,%2,%3}, {%4,%5,%6,%7}, {%8,%9}, {%0,%1,%2,%3};"
                        : "+f"(acc[mf][nf][0]), "+f"(acc[mf][nf][1]),
                          "+f"(acc[mf][nf][2]), "+f"(acc[mf][nf][3])
                        : "r"(a[mf][0]), "r"(a[mf][1]), "r"(a[mf][2]), "r"(a[mf][3]),
                          "r"(b[nq][base]), "r"(b[nq][base + 1]));
                }
        }
    }

    // -----------------------------------------------------------------------
    // Epilogue. sim = 2*acc. Off-diag tiles: accumulate exp into row sums AND
    // column sums (mirror tile). Diag tiles: row sums only, mask c==r.
    // pos pairs only occur in off-diag tiles; one write covers (r,c) and (c,r).
    // -----------------------------------------------------------------------
    const int qrow = lid >> 2, qcol = lid & 3;
    float rs[4] = {0.f, 0.f, 0.f, 0.f};   // [mf*2+sub]
    float cs[8][2];
    #pragma unroll
    for (int nf = 0; nf < 8; nf++) { cs[nf][0] = 0.f; cs[nf][1] = 0.f; }

    #pragma unroll
    for (int mf = 0; mf < 2; mf++) {
        #pragma unroll
        for (int sub = 0; sub < 2; sub++) {
            const int r = r0 + warp_m * 32 + mf * 16 + sub * 8 + qrow;
            const int partner = (r < B) ? (r + B) : (r - B);
            #pragma unroll
            for (int nf = 0; nf < 8; nf++) {
                #pragma unroll
                for (int e = 0; e < 2; e++) {
                    const int c = c0 + warp_n * 64 + nf * 8 + qcol * 2 + e;
                    const float sim = 2.0f * acc[mf][nf][sub * 2 + e];
                    float ex = fast_exp_nonpos(sim - 2.0f);
                    if (diag && c == r) ex = 0.0f;
                    rs[mf * 2 + sub] += ex;
                    if (!diag) cs[nf][e] += ex;
                    if (c == partner) { g_pos[r] = sim; g_pos[c] = sim; }
                }
            }
        }
    }

    // row sums: reduce across qcol (lanes 1,2)
    #pragma unroll
    for (int i = 0; i < 4; i++) {
        rs[i] += __shfl_xor_sync(0xffffffffu, rs[i], 1);
        rs[i] += __shfl_xor_sync(0xffffffffu, rs[i], 2);
    }
    if (qcol == 0) {
        #pragma unroll
        for (int mf = 0; mf < 2; mf++)
            #pragma unroll
            for (int sub = 0; sub < 2; sub++) {
                const int r = r0 + warp_m * 32 + mf * 16 + sub * 8 + qrow;
                atomicAdd(&g_S[r], rs[mf * 2 + sub]);
            }
    }

    // col sums: reduce across qrow (lanes 4,8,16); lanes 0..3 write
    if (!diag) {
        #pragma unroll
        for (int nf = 0; nf < 8; nf++) {
            #pragma unroll
            for (int e = 0; e < 2; e++) {
                float v = cs[nf][e];
                v += __shfl_xor_sync(0xffffffffu, v, 4);
                v += __shfl_xor_sync(0xffffffffu, v, 8);
                v += __shfl_xor_sync(0xffffffffu, v, 16);
                if (lid < 4) {
                    const int c = c0 + warp_n * 64 + nf * 8 + qcol * 2 + e;
                    atomicAdd(&g_S[c], v);
                }
            }
        }
    }
}

// ---------------------------------------------------------------------------
// Kernel 3: loss = (1/N) * sum_i (2 + log(S_i) - pos_i)
// ---------------------------------------------------------------------------
__global__ void k_final(float* __restrict__ out, int Nn) {
    int t = threadIdx.x;
    float s = 0.0f;
    for (int i = t; i < Nn; i += 1024)
        s += 2.0f + logf(g_S[i]) - g_pos[i];
    #pragma unroll
    for (int o = 16; o > 0; o >>= 1) s += __shfl_xor_sync(0xffffffffu, s, o);
    __shared__ float ws[32];
    if ((t & 31) == 0) ws[t >> 5] = s;
    __syncthreads();
    if (t < 32) {
        float x = ws[t];
        #pragma unroll
        for (int o = 16; o > 0; o >>= 1) x += __shfl_xor_sync(0xffffffffu, x, o);
        if (t == 0) out[0] = x / (float)Nn;
    }
}

// ---------------------------------------------------------------------------
extern "C" void kernel_launch(void* const* d_in, const int* in_sizes, int n_in,
                              void* d_out, int out_size) {
    const float* zi = (const float*)d_in[0];
    const float* zj = (const float*)d_in[1];
    int B  = in_sizes[0] / D;   // 4096
    int Nn = 2 * B;             // 8192

    const int smem_bytes = 4 * CH_BYTES;   // 139264
    cudaFuncSetAttribute(k_simgemm_sym,
                         cudaFuncAttributeMaxDynamicSharedMemorySize, smem_bytes);

    k_normalize<<<Nn, 256>>>(zi, zj, B);
    const int ntiles = Nn / TILE;                 // 64
    const int nblocks = ntiles * (ntiles + 1) / 2; // 2080
    k_simgemm_sym<<<nblocks, 256, smem_bytes>>>(Nn, B);
    k_final<<<1, 1024>>>((float*)d_out, Nn);
}

// round 8
// speedup vs baseline: 10.1322x; 1.3593x over previous
#include <cuda_runtime.h>
#include <cuda_bf16.h>
#include <cstdint>
#include <math.h>

#define D 256
#define MAXN 8192
#define TILE 128
#define KC 64                        // K-chunk elems
#define CHK 72                       // smem row: 72 bf16 = 144B (9*16, cp.async-aligned;
                                     // 36 words == 4 mod 32 -> conflict-free ldmatrix)
#define ST_ELEMS (TILE * CHK)        // one stage = 9216 elems
#define ST_BYTES (ST_ELEMS * 2)      // 18432 B

// Scratch (__device__ globals: allocation-free rule)
__device__ __nv_bfloat16 g_znb[MAXN * D];   // normalized rows, bf16 (4 MB)
__device__ float g_S[MAXN];                 // sum_{j!=i} exp(sim_ij - 2)
__device__ float g_pos[MAXN];               // sim[i, partner(i)]

__device__ __forceinline__ uint32_t smem_u32(const void* p) {
    uint32_t a;
    asm("{ .reg .u64 t; cvta.to.shared.u64 t, %1; cvt.u32.u64 %0, t; }"
        : "=r"(a) : "l"(p));
    return a;
}

__device__ __forceinline__ void cp_async16(uint32_t dst, const void* src) {
    asm volatile("cp.async.cg.shared.global [%0], [%1], 16;" :: "r"(dst), "l"(src));
}
#define CP_COMMIT() asm volatile("cp.async.commit_group;" ::: "memory")
#define CP_WAIT(n)  asm volatile("cp.async.wait_group %0;" :: "n"(n) : "memory")

// ---------------------------------------------------------------------------
// exp(x), x in ~[-4, 0+eps], FMA-pipe polynomial (avoids MUFU wall)
// ---------------------------------------------------------------------------
__device__ __forceinline__ float fast_exp_nonpos(float x) {
    float t  = x * 1.4426950408889634f;
    float fi = rintf(t);
    float f  = t - fi;
    float p  = 1.5403530394e-4f;
    p = fmaf(p, f, 1.3333558147e-3f);
    p = fmaf(p, f, 9.6181291071e-3f);
    p = fmaf(p, f, 5.5504108665e-2f);
    p = fmaf(p, f, 2.4022650696e-1f);
    p = fmaf(p, f, 6.9314718056e-1f);
    p = fmaf(p, f, 1.0f);
    int i = (int)fi;
    return p * __int_as_float((i + 127) << 23);
}

// ---------------------------------------------------------------------------
// Kernel 1: normalize rows -> bf16. Warp per row, float4 loads, 8 rows/block.
// ---------------------------------------------------------------------------
__global__ __launch_bounds__(256)
void k_normalize(const float* __restrict__ zi,
                 const float* __restrict__ zj, int B) {
    const int w   = threadIdx.x >> 5;       // 0..7
    const int lid = threadIdx.x & 31;
    const int row = blockIdx.x * 8 + w;
    const float* src = (row < B) ? (zi + (size_t)row * D)
                                 : (zj + (size_t)(row - B) * D);
    float4 v0 = *reinterpret_cast<const float4*>(src + lid * 8);
    float4 v1 = *reinterpret_cast<const float4*>(src + lid * 8 + 4);
    float s = v0.x*v0.x + v0.y*v0.y + v0.z*v0.z + v0.w*v0.w
            + v1.x*v1.x + v1.y*v1.y + v1.z*v1.z + v1.w*v1.w;
    #pragma unroll
    for (int o = 16; o > 0; o >>= 1) s += __shfl_xor_sync(0xffffffffu, s, o);
    float inv = 1.0f / fmaxf(sqrtf(s), 1e-8f);

    __nv_bfloat162 p0 = __floats2bfloat162_rn(v0.x * inv, v0.y * inv);
    __nv_bfloat162 p1 = __floats2bfloat162_rn(v0.z * inv, v0.w * inv);
    __nv_bfloat162 p2 = __floats2bfloat162_rn(v1.x * inv, v1.y * inv);
    __nv_bfloat162 p3 = __floats2bfloat162_rn(v1.z * inv, v1.w * inv);
    uint4 pk;
    pk.x = *reinterpret_cast<uint32_t*>(&p0);
    pk.y = *reinterpret_cast<uint32_t*>(&p1);
    pk.z = *reinterpret_cast<uint32_t*>(&p2);
    pk.w = *reinterpret_cast<uint32_t*>(&p3);
    *reinterpret_cast<uint4*>(&g_znb[(size_t)row * D + lid * 8]) = pk;
    if (lid == 0) { g_S[row] = 0.0f; g_pos[row] = 0.0f; }
}

// ---------------------------------------------------------------------------
// Kernel 2: lower-triangle 128x128 tiles (2080 CTAs), bf16 mma.sync.
// K streamed as 4 chunks of 64, double-buffered cp.async -> 72KB smem
// -> 2 CTAs/SM so epilogue/load of one CTA overlaps MMA of the other.
// ---------------------------------------------------------------------------
__global__ __launch_bounds__(256, 2)
void k_simgemm_sym(int Nn, int B) {
    extern __shared__ __nv_bfloat16 smem[];
    __nv_bfloat16* As = smem;                     // 2 stages
    __nv_bfloat16* Bs = smem + 2 * ST_ELEMS;      // 2 stages

    // decode lower-triangle tile (by >= bx)
    int idx = blockIdx.x;
    int by = (int)((sqrtf(8.0f * (float)idx + 1.0f) - 1.0f) * 0.5f);
    while ((by + 1) * (by + 2) / 2 <= idx) by++;
    while (by * (by + 1) / 2 > idx) by--;
    int bx = idx - by * (by + 1) / 2;
    const int r0 = by * TILE, c0 = bx * TILE;
    const bool diag = (by == bx);

    const int tid = threadIdx.x;
    const int wid = tid >> 5, lid = tid & 31;

    // chunk loader: 128 rows x 64 elems per matrix = 1024 uint4 -> 4/thread
    auto issue_chunk = [&](int ch) {
        const int buf = ch & 1;
        #pragma unroll
        for (int q = 0; q < 4; q++) {
            int li  = tid + q * 256;            // 0..1023
            int row = li >> 3;                  // 0..127
            int kq  = (li & 7) << 3;            // 0..56
            uint32_t dstA = smem_u32(&As[buf * ST_ELEMS + row * CHK + kq]);
            uint32_t dstB = smem_u32(&Bs[buf * ST_ELEMS + row * CHK + kq]);
            cp_async16(dstA, &g_znb[(size_t)(r0 + row) * D + ch * KC + kq]);
            cp_async16(dstB, &g_znb[(size_t)(c0 + row) * D + ch * KC + kq]);
        }
        CP_COMMIT();
    };

    issue_chunk(0);
    issue_chunk(1);

    const int warp_m = wid & 3;
    const int warp_n = wid >> 2;

    // per-lane ldmatrix base addresses (stage 0)
    uint32_t aAddr[2];
    #pragma unroll
    for (int mf = 0; mf < 2; mf++) {
        int row = warp_m * 32 + mf * 16 + (lid & 15);
        int col = (lid >> 4) << 3;
        aAddr[mf] = smem_u32(&As[row * CHK + col]);
    }
    uint32_t bAddr[4];
    #pragma unroll
    for (int nq = 0; nq < 4; nq++) {
        int row = warp_n * 64 + nq * 16 + ((lid >> 4) << 3) + (lid & 7);
        int col = (lid & 8);
        bAddr[nq] = smem_u32(&Bs[row * CHK + col]);
    }

    float acc[2][8][4];
    #pragma unroll
    for (int i = 0; i < 2; i++)
        #pragma unroll
        for (int j = 0; j < 8; j++)
            #pragma unroll
            for (int e = 0; e < 4; e++) acc[i][j][e] = 0.0f;

    #pragma unroll
    for (int ch = 0; ch < 4; ch++) {
        if (ch == 3) CP_WAIT(0); else CP_WAIT(1);
        __syncthreads();
        const uint32_t cb = (uint32_t)(ch & 1) * ST_BYTES;
        #pragma unroll
        for (int ks = 0; ks < 4; ks++) {          // 4 k-steps of 16 per chunk
            const uint32_t kb = cb + ks * 32;
            uint32_t a[2][4], b[4][4];
            #pragma unroll
            for (int mf = 0; mf < 2; mf++)
                asm volatile("ldmatrix.sync.aligned.m8n8.x4.shared.b16 {%0,%1,%2,%3}, [%4];"
                             : "=r"(a[mf][0]), "=r"(a[mf][1]), "=r"(a[mf][2]), "=r"(a[mf][3])
                             : "r"(aAddr[mf] + kb));
            #pragma unroll
            for (int nq = 0; nq < 4; nq++)
                asm volatile("ldmatrix.sync.aligned.m8n8.x4.shared.b16 {%0,%1,%2,%3}, [%4];"
                             : "=r"(b[nq][0]), "=r"(b[nq][1]), "=r"(b[nq][2]), "=r"(b[nq][3])
                             : "r"(bAddr[nq] + kb));
            #pragma unroll
            for (int mf = 0; mf < 2; mf++)
                #pragma unroll
                for (int nf = 0; nf < 8; nf++) {
                    const int nq = nf >> 1, base = (nf & 1) * 2;
                    asm volatile(
                        "mma.sync.aligned.m16n8k16.row.col.f32.bf16.bf16.f32 "
                        "{%0,%1,%2,%3}, {%4,%5,%6,%7}, {%8,%9}, {%0,%1,%2,%3};"
                        : "+f"(acc[mf][nf][0]), "+f"(acc[mf][nf][1]),
                          "+f"(acc[mf][nf][2]), "+f"(acc[mf][nf][3])
                        : "r"(a[mf][0]), "r"(a[mf][1]), "r"(a[mf][2]), "r"(a[mf][3]),
                          "r"(b[nq][base]), "r"(b[nq][base + 1]));
                }
        }
        __syncthreads();           // all warps done reading this stage
        if (ch < 2) issue_chunk(ch + 2);
    }

    // -----------------------------------------------------------------------
    // Epilogue. sim = 2*acc. Off-diag: exp into row sums AND column sums
    // (mirror tile). Diag: row sums only, mask c==r. One pos write covers
    // (r,c) and (c,r); pos pairs only occur in tiles with by == bx+32.
    // -----------------------------------------------------------------------
    const int qrow = lid >> 2, qcol = lid & 3;
    const bool has_pos = (by == bx + (B / TILE));
    float rs[4] = {0.f, 0.f, 0.f, 0.f};
    float cs[8][2];
    #pragma unroll
    for (int nf = 0; nf < 8; nf++) { cs[nf][0] = 0.f; cs[nf][1] = 0.f; }

    #pragma unroll
    for (int mf = 0; mf < 2; mf++) {
        #pragma unroll
        for (int sub = 0; sub < 2; sub++) {
            const int r = r0 + warp_m * 32 + mf * 16 + sub * 8 + qrow;
            const int partner = (r < B) ? (r + B) : (r - B);
            #pragma unroll
            for (int nf = 0; nf < 8; nf++) {
                #pragma unroll
                for (int e = 0; e < 2; e++) {
                    const int c = c0 + warp_n * 64 + nf * 8 + qcol * 2 + e;
                    const float sim = 2.0f * acc[mf][nf][sub * 2 + e];
                    float ex = fast_exp_nonpos(sim - 2.0f);
                    if (diag && c == r) ex = 0.0f;
                    rs[mf * 2 + sub] += ex;
                    if (!diag) cs[nf][e] += ex;
                    if (has_pos && c == partner) { g_pos[r] = sim; g_pos[c] = sim; }
                }
            }
        }
    }

    // row sums: reduce across qcol (lanes 1,2)
    #pragma unroll
    for (int i = 0; i < 4; i++) {
        rs[i] += __shfl_xor_sync(0xffffffffu, rs[i], 1);
        rs[i] += __shfl_xor_sync(0xffffffffu, rs[i], 2);
    }
    if (qcol == 0) {
        #pragma unroll
        for (int mf = 0; mf < 2; mf++)
            #pragma unroll
            for (int sub = 0; sub < 2; sub++) {
                const int r = r0 + warp_m * 32 + mf * 16 + sub * 8 + qrow;
                atomicAdd(&g_S[r], rs[mf * 2 + sub]);
            }
    }

    // col sums: reduce across qrow (lanes 4,8,16); lanes 0..3 write
    if (!diag) {
        #pragma unroll
        for (int nf = 0; nf < 8; nf++) {
            #pragma unroll
            for (int e = 0; e < 2; e++) {
                float v = cs[nf][e];
                v += __shfl_xor_sync(0xffffffffu, v, 4);
                v += __shfl_xor_sync(0xffffffffu, v, 8);
                v += __shfl_xor_sync(0xffffffffu, v, 16);
                if (lid < 4) {
                    const int c = c0 + warp_n * 64 + nf * 8 + qcol * 2 + e;
                    atomicAdd(&g_S[c], v);
                }
            }
        }
    }
}

// ---------------------------------------------------------------------------
// Kernel 3: loss = (1/N) * sum_i (2 + log(S_i) - pos_i)
// ---------------------------------------------------------------------------
__global__ void k_final(float* __restrict__ out, int Nn) {
    int t = threadIdx.x;
    float s = 0.0f;
    for (int i = t; i < Nn; i += 1024)
        s += 2.0f + logf(g_S[i]) - g_pos[i];
    #pragma unroll
    for (int o = 16; o > 0; o >>= 1) s += __shfl_xor_sync(0xffffffffu, s, o);
    __shared__ float ws[32];
    if ((t & 31) == 0) ws[t >> 5] = s;
    __syncthreads();
    if (t < 32) {
        float x = ws[t];
        #pragma unroll
        for (int o = 16; o > 0; o >>= 1) x += __shfl_xor_sync(0xffffffffu, x, o);
        if (t == 0) out[0] = x / (float)Nn;
    }
}

// ---------------------------------------------------------------------------
extern "C" void kernel_launch(void* const* d_in, const int* in_sizes, int n_in,
                              void* d_out, int out_size) {
    const float* zi = (const float*)d_in[0];
    const float* zj = (const float*)d_in[1];
    int B  = in_sizes[0] / D;   // 4096
    int Nn = 2 * B;             // 8192

    const int smem_bytes = 4 * ST_BYTES;   // 73728
    cudaFuncSetAttribute(k_simgemm_sym,
                         cudaFuncAttributeMaxDynamicSharedMemorySize, smem_bytes);

    k_normalize<<<Nn / 8, 256>>>(zi, zj, B);
    const int ntiles = Nn / TILE;                  // 64
    const int nblocks = ntiles * (ntiles + 1) / 2; // 2080
    k_simgemm_sym<<<nblocks, 256, smem_bytes>>>(Nn, B);
    k_final<<<1, 1024>>>((float*)d_out, Nn);
}

// round 9
// speedup vs baseline: 10.3772x; 1.0242x over previous
#include <cuda_runtime.h>
#include <cuda_bf16.h>
#include <cstdint>
#include <math.h>

#define D 256
#define MAXN 8192
#define TILE 128
#define CHKB 144                     // smem row bytes: 144 = 9*16 (cp.async-aligned);
                                     // 36 words == 4 mod 32 -> conflict-free ldmatrix
#define ST_BYTES (TILE * CHKB)       // one stage = 18432 B (K-chunk of 128 fp8)

// Scratch (__device__ globals: allocation-free rule)
__device__ uint8_t g_znq[MAXN * D];  // normalized rows, e4m3 (2 MB)
__device__ float g_S[MAXN];          // sum_{j!=i} exp(sim_ij - 2)
__device__ float g_pos[MAXN];        // sim[i, partner(i)]

__device__ __forceinline__ uint32_t smem_u32(const void* p) {
    uint32_t a;
    asm("{ .reg .u64 t; cvta.to.shared.u64 t, %1; cvt.u32.u64 %0, t; }"
        : "=r"(a) : "l"(p));
    return a;
}

__device__ __forceinline__ void cp_async16(uint32_t dst, const void* src) {
    asm volatile("cp.async.cg.shared.global [%0], [%1], 16;" :: "r"(dst), "l"(src));
}
#define CP_COMMIT() asm volatile("cp.async.commit_group;" ::: "memory")
#define CP_WAIT(n)  asm volatile("cp.async.wait_group %0;" :: "n"(n) : "memory")

// ---------------------------------------------------------------------------
// exp(x), x in ~[-4.1, 0.1], FMA-pipe polynomial (avoids MUFU wall)
// ---------------------------------------------------------------------------
__device__ __forceinline__ float fast_exp_nonpos(float x) {
    float t  = x * 1.4426950408889634f;
    float fi = rintf(t);
    float f  = t - fi;
    float p  = 1.5403530394e-4f;
    p = fmaf(p, f, 1.3333558147e-3f);
    p = fmaf(p, f, 9.6181291071e-3f);
    p = fmaf(p, f, 5.5504108665e-2f);
    p = fmaf(p, f, 2.4022650696e-1f);
    p = fmaf(p, f, 6.9314718056e-1f);
    p = fmaf(p, f, 1.0f);
    int i = (int)fi;
    return p * __int_as_float((i + 127) << 23);
}

// ---------------------------------------------------------------------------
// Kernel 1: normalize rows -> e4m3. Warp per row, float4 loads, 8 rows/block.
// (k-pairing inside e4m3x2 packs is applied identically to all rows, and the
//  dot product is invariant under any k-permutation shared by A and B.)
// ---------------------------------------------------------------------------
__global__ __launch_bounds__(256)
void k_normalize(const float* __restrict__ zi,
                 const float* __restrict__ zj, int B) {
    const int w   = threadIdx.x >> 5;
    const int lid = threadIdx.x & 31;
    const int row = blockIdx.x * 8 + w;
    const float* src = (row < B) ? (zi + (size_t)row * D)
                                 : (zj + (size_t)(row - B) * D);
    float4 v0 = *reinterpret_cast<const float4*>(src + lid * 8);
    float4 v1 = *reinterpret_cast<const float4*>(src + lid * 8 + 4);
    float s = v0.x*v0.x + v0.y*v0.y + v0.z*v0.z + v0.w*v0.w
            + v1.x*v1.x + v1.y*v1.y + v1.z*v1.z + v1.w*v1.w;
    #pragma unroll
    for (int o = 16; o > 0; o >>= 1) s += __shfl_xor_sync(0xffffffffu, s, o);
    float inv = 1.0f / fmaxf(sqrtf(s), 1e-8f);

    uint16_t h0, h1, h2, h3;
    asm("cvt.rn.satfinite.e4m3x2.f32 %0, %1, %2;" : "=h"(h0) : "f"(v0.y*inv), "f"(v0.x*inv));
    asm("cvt.rn.satfinite.e4m3x2.f32 %0, %1, %2;" : "=h"(h1) : "f"(v0.w*inv), "f"(v0.z*inv));
    asm("cvt.rn.satfinite.e4m3x2.f32 %0, %1, %2;" : "=h"(h2) : "f"(v1.y*inv), "f"(v1.x*inv));
    asm("cvt.rn.satfinite.e4m3x2.f32 %0, %1, %2;" : "=h"(h3) : "f"(v1.w*inv), "f"(v1.z*inv));
    uint2 pk;
    pk.x = (uint32_t)h0 | ((uint32_t)h1 << 16);
    pk.y = (uint32_t)h2 | ((uint32_t)h3 << 16);
    *reinterpret_cast<uint2*>(&g_znq[(size_t)row * D + lid * 8]) = pk;
    if (lid == 0) { g_S[row] = 0.0f; g_pos[row] = 0.0f; }
}

// ---------------------------------------------------------------------------
// Kernel 2: lower-triangle 128x128 tiles (2080 CTAs), e4m3 mma.sync.m16n8k32.
// K=256 as 2 chunks of 128 bytes, double-buffered cp.async; 72KB smem ->
// 2 CTAs/SM (epilogue of one CTA overlaps MMA of the other).
// Byte-level fragment layout of e4m3 k32 == bf16 k16, so the ldmatrix
// addressing is the R8 scheme with elems -> bytes.
// ---------------------------------------------------------------------------
__global__ __launch_bounds__(256, 2)
void k_simgemm_sym(int Nn, int B) {
    extern __shared__ uint8_t smem[];
    uint8_t* As = smem;                      // 2 stages
    uint8_t* Bs = smem + 2 * ST_BYTES;       // 2 stages

    // decode lower-triangle tile (by >= bx)
    int idx = blockIdx.x;
    int by = (int)((sqrtf(8.0f * (float)idx + 1.0f) - 1.0f) * 0.5f);
    while ((by + 1) * (by + 2) / 2 <= idx) by++;
    while (by * (by + 1) / 2 > idx) by--;
    int bx = idx - by * (by + 1) / 2;
    const int r0 = by * TILE, c0 = bx * TILE;
    const bool diag = (by == bx);

    const int tid = threadIdx.x;
    const int wid = tid >> 5, lid = tid & 31;

    // chunk loader: 128 rows x 128 B per matrix = 1024 x 16B -> 4/thread each
    auto issue_chunk = [&](int ch) {
        #pragma unroll
        for (int q = 0; q < 4; q++) {
            int li  = tid + q * 256;            // 0..1023
            int row = li >> 3;                  // 0..127
            int seg = (li & 7) << 4;            // 0..112 bytes
            uint32_t dstA = smem_u32(&As[ch * ST_BYTES + row * CHKB + seg]);
            uint32_t dstB = smem_u32(&Bs[ch * ST_BYTES + row * CHKB + seg]);
            cp_async16(dstA, &g_znq[(size_t)(r0 + row) * D + ch * 128 + seg]);
            cp_async16(dstB, &g_znq[(size_t)(c0 + row) * D + ch * 128 + seg]);
        }
        CP_COMMIT();
    };

    issue_chunk(0);
    issue_chunk(1);

    const int warp_m = wid & 3;
    const int warp_n = wid >> 2;

    // per-lane ldmatrix base addresses (stage 0), byte offsets
    uint32_t aAddr[2];
    #pragma unroll
    for (int mf = 0; mf < 2; mf++) {
        int row = warp_m * 32 + mf * 16 + (lid & 15);
        int colb = (lid >> 4) << 4;             // 0 or 16
        aAddr[mf] = smem_u32(&As[row * CHKB + colb]);
    }
    uint32_t bAddr[4];
    #pragma unroll
    for (int nq = 0; nq < 4; nq++) {
        int row = warp_n * 64 + nq * 16 + ((lid >> 4) << 3) + (lid & 7);
        int colb = (lid & 8) << 1;              // 0 or 16
        bAddr[nq] = smem_u32(&Bs[row * CHKB + colb]);
    }

    float acc[2][8][4];
    #pragma unroll
    for (int i = 0; i < 2; i++)
        #pragma unroll
        for (int j = 0; j < 8; j++)
            #pragma unroll
            for (int e = 0; e < 4; e++) acc[i][j][e] = 0.0f;

    #pragma unroll
    for (int ch = 0; ch < 2; ch++) {
        if (ch == 0) CP_WAIT(1); else CP_WAIT(0);
        __syncthreads();
        const uint32_t cb = (uint32_t)ch * ST_BYTES;
        #pragma unroll
        for (int ks = 0; ks < 4; ks++) {          // 4 k-steps of 32 per chunk
            const uint32_t kb = cb + ks * 32;
            uint32_t a[2][4], b[4][4];
            #pragma unroll
            for (int mf = 0; mf < 2; mf++)
                asm volatile("ldmatrix.sync.aligned.m8n8.x4.shared.b16 {%0,%1,%2,%3}, [%4];"
                             : "=r"(a[mf][0]), "=r"(a[mf][1]), "=r"(a[mf][2]), "=r"(a[mf][3])
                             : "r"(aAddr[mf] + kb));
            #pragma unroll
            for (int nq = 0; nq < 4; nq++)
                asm volatile("ldmatrix.sync.aligned.m8n8.x4.shared.b16 {%0,%1,%2,%3}, [%4];"
                             : "=r"(b[nq][0]), "=r"(b[nq][1]), "=r"(b[nq][2]), "=r"(b[nq][3])
                             : "r"(bAddr[nq] + kb));
            #pragma unroll
            for (int mf = 0; mf < 2; mf++)
                #pragma unroll
                for (int nf = 0; nf < 8; nf++) {
                    const int nq = nf >> 1, base = (nf & 1) * 2;
                    asm volatile(
                        "mma.sync.aligned.m16n8k32.row.col.f32.e4m3.e4m3.f32 "
                        "{%0,%1,%2,%3}, {%4,%5,%6,%7}, {%8,%9}, {%0,%1,%2,%3};"
                        : "+f"(acc[mf][nf][0]), "+f"(acc[mf][nf][1]),
                          "+f"(acc[mf][nf][2]), "+f"(acc[mf][nf][3])
                        : "r"(a[mf][0]), "r"(a[mf][1]), "r"(a[mf][2]), "r"(a[mf][3]),
                          "r"(b[nq][base]), "r"(b[nq][base + 1]));
                }
        }
        __syncthreads();
    }

    // -----------------------------------------------------------------------
    // Epilogue. sim = 2*acc. Off-diag: exp into row sums AND column sums
    // (mirror tile). Diag: row sums only, mask c==r. One pos write covers
    // (r,c) and (c,r); pos pairs only occur in tiles with by == bx + B/TILE.
    // -----------------------------------------------------------------------
    const int qrow = lid >> 2, qcol = lid & 3;
    const bool has_pos = (by == bx + (B / TILE));
    float rs[4] = {0.f, 0.f, 0.f, 0.f};
    float cs[8][2];
    #pragma unroll
    for (int nf = 0; nf < 8; nf++) { cs[nf][0] = 0.f; cs[nf][1] = 0.f; }

    #pragma unroll
    for (int mf = 0; mf < 2; mf++) {
        #pragma unroll
        for (int sub = 0; sub < 2; sub++) {
            const int r = r0 + warp_m * 32 + mf * 16 + sub * 8 + qrow;
            const int partner = (r < B) ? (r + B) : (r - B);
            #pragma unroll
            for (int nf = 0; nf < 8; nf++) {
                #pragma unroll
                for (int e = 0; e < 2; e++) {
                    const int c = c0 + warp_n * 64 + nf * 8 + qcol * 2 + e;
                    const float sim = 2.0f * acc[mf][nf][sub * 2 + e];
                    float ex = fast_exp_nonpos(sim - 2.0f);
                    if (diag && c == r) ex = 0.0f;
                    rs[mf * 2 + sub] += ex;
                    if (!diag) cs[nf][e] += ex;
                    if (has_pos && c == partner) { g_pos[r] = sim; g_pos[c] = sim; }
                }
            }
        }
    }

    // row sums: reduce across qcol (lanes 1,2)
    #pragma unroll
    for (int i = 0; i < 4; i++) {
        rs[i] += __shfl_xor_sync(0xffffffffu, rs[i], 1);
        rs[i] += __shfl_xor_sync(0xffffffffu, rs[i], 2);
    }
    if (qcol == 0) {
        #pragma unroll
        for (int mf = 0; mf < 2; mf++)
            #pragma unroll
            for (int sub = 0; sub < 2; sub++) {
                const int r = r0 + warp_m * 32 + mf * 16 + sub * 8 + qrow;
                atomicAdd(&g_S[r], rs[mf * 2 + sub]);
            }
    }

    // col sums: reduce across qrow (lanes 4,8,16); lanes 0..3 write
    if (!diag) {
        #pragma unroll
        for (int nf = 0; nf < 8; nf++) {
            #pragma unroll
            for (int e = 0; e < 2; e++) {
                float v = cs[nf][e];
                v += __shfl_xor_sync(0xffffffffu, v, 4);
                v += __shfl_xor_sync(0xffffffffu, v, 8);
                v += __shfl_xor_sync(0xffffffffu, v, 16);
                if (lid < 4) {
                    const int c = c0 + warp_n * 64 + nf * 8 + qcol * 2 + e;
                    atomicAdd(&g_S[c], v);
                }
            }
        }
    }
}

// ---------------------------------------------------------------------------
// Kernel 3: loss = (1/N) * sum_i (2 + log(S_i) - pos_i)
// ---------------------------------------------------------------------------
__global__ void k_final(float* __restrict__ out, int Nn) {
    int t = threadIdx.x;
    float s = 0.0f;
    for (int i = t; i < Nn; i += 1024)
        s += 2.0f + logf(g_S[i]) - g_pos[i];
    #pragma unroll
    for (int o = 16; o > 0; o >>= 1) s += __shfl_xor_sync(0xffffffffu, s, o);
    __shared__ float ws[32];
    if ((t & 31) == 0) ws[t >> 5] = s;
    __syncthreads();
    if (t < 32) {
        float x = ws[t];
        #pragma unroll
        for (int o = 16; o > 0; o >>= 1) x += __shfl_xor_sync(0xffffffffu, x, o);
        if (t == 0) out[0] = x / (float)Nn;
    }
}

// ---------------------------------------------------------------------------
extern "C" void kernel_launch(void* const* d_in, const int* in_sizes, int n_in,
                              void* d_out, int out_size) {
    const float* zi = (const float*)d_in[0];
    const float* zj = (const float*)d_in[1];
    int B  = in_sizes[0] / D;   // 4096
    int Nn = 2 * B;             // 8192

    const int smem_bytes = 4 * ST_BYTES;   // 73728
    cudaFuncSetAttribute(k_simgemm_sym,
                         cudaFuncAttributeMaxDynamicSharedMemorySize, smem_bytes);

    k_normalize<<<Nn / 8, 256>>>(zi, zj, B);
    const int ntiles = Nn / TILE;                  // 64
    const int nblocks = ntiles * (ntiles + 1) / 2; // 2080
    k_simgemm_sym<<<nblocks, 256, smem_bytes>>>(Nn, B);
    k_final<<<1, 1024>>>((float*)d_out, Nn);
}

// round 10
// speedup vs baseline: 13.7693x; 1.3269x over previous
#include <cuda_runtime.h>
#include <cstdint>
#include <math.h>

#define D 256
#define MAXN 8192
#define TILE 128
#define CHKB 144                     // smem row bytes: 144 = 9*16 (cp.async-aligned);
                                     // 36 words == 4 mod 32 -> conflict-free ldmatrix
#define ST_BYTES (TILE * CHKB)       // one stage = 18432 B (K-chunk of 128 s8)

// Scratch (__device__ globals: allocation-free rule)
__device__ int8_t g_znq[MAXN * D];   // normalized rows, s8 (scale 127), 2 MB
__device__ float g_S[MAXN];          // sum_{j!=i} exp(sim_ij - 2)
__device__ float g_pos[MAXN];        // sim[i, partner(i)]

__device__ __forceinline__ uint32_t smem_u32(const void* p) {
    uint32_t a;
    asm("{ .reg .u64 t; cvta.to.shared.u64 t, %1; cvt.u32.u64 %0, t; }"
        : "=r"(a) : "l"(p));
    return a;
}

__device__ __forceinline__ void cp_async16(uint32_t dst, const void* src) {
    asm volatile("cp.async.cg.shared.global [%0], [%1], 16;" :: "r"(dst), "l"(src));
}
#define CP_COMMIT() asm volatile("cp.async.commit_group;" ::: "memory")
#define CP_WAIT(n)  asm volatile("cp.async.wait_group %0;" :: "n"(n) : "memory")

// ---------------------------------------------------------------------------
// exp(x), x in ~[-4.1, 0.1], FMA-pipe polynomial (avoids MUFU wall)
// ---------------------------------------------------------------------------
__device__ __forceinline__ float fast_exp_nonpos(float x) {
    float t  = x * 1.4426950408889634f;
    float fi = rintf(t);
    float f  = t - fi;
    float p  = 1.5403530394e-4f;
    p = fmaf(p, f, 1.3333558147e-3f);
    p = fmaf(p, f, 9.6181291071e-3f);
    p = fmaf(p, f, 5.5504108665e-2f);
    p = fmaf(p, f, 2.4022650696e-1f);
    p = fmaf(p, f, 6.9314718056e-1f);
    p = fmaf(p, f, 1.0f);
    int i = (int)fi;
    return p * __int_as_float((i + 127) << 23);
}

// ---------------------------------------------------------------------------
// Kernel 1: normalize rows -> s8 (scale 127). Warp per row, 8 rows/block.
// ---------------------------------------------------------------------------
__global__ __launch_bounds__(256)
void k_normalize(const float* __restrict__ zi,
                 const float* __restrict__ zj, int B) {
    const int w   = threadIdx.x >> 5;
    const int lid = threadIdx.x & 31;
    const int row = blockIdx.x * 8 + w;
    const float* src = (row < B) ? (zi + (size_t)row * D)
                                 : (zj + (size_t)(row - B) * D);
    float4 v0 = *reinterpret_cast<const float4*>(src + lid * 8);
    float4 v1 = *reinterpret_cast<const float4*>(src + lid * 8 + 4);
    float s = v0.x*v0.x + v0.y*v0.y + v0.z*v0.z + v0.w*v0.w
            + v1.x*v1.x + v1.y*v1.y + v1.z*v1.z + v1.w*v1.w;
    #pragma unroll
    for (int o = 16; o > 0; o >>= 1) s += __shfl_xor_sync(0xffffffffu, s, o);
    float q = 127.0f / fmaxf(sqrtf(s), 1e-8f);

    int i0 = __float2int_rn(v0.x * q), i1 = __float2int_rn(v0.y * q);
    int i2 = __float2int_rn(v0.z * q), i3 = __float2int_rn(v0.w * q);
    int i4 = __float2int_rn(v1.x * q), i5 = __float2int_rn(v1.y * q);
    int i6 = __float2int_rn(v1.z * q), i7 = __float2int_rn(v1.w * q);
    uint2 pk;
    pk.x = (uint32_t)(i0 & 255) | ((uint32_t)(i1 & 255) << 8) |
           ((uint32_t)(i2 & 255) << 16) | ((uint32_t)(i3 & 255) << 24);
    pk.y = (uint32_t)(i4 & 255) | ((uint32_t)(i5 & 255) << 8) |
           ((uint32_t)(i6 & 255) << 16) | ((uint32_t)(i7 & 255) << 24);
    *reinterpret_cast<uint2*>(&g_znq[(size_t)row * D + lid * 8]) = pk;
    if (lid == 0) { g_S[row] = 0.0f; g_pos[row] = 0.0f; }
}

// ---------------------------------------------------------------------------
// Kernel 2: lower-triangle 128x128 tiles (2080 CTAs), s8 mma.sync.m16n8k32.
// K=256 as 2 chunks of 128 B, double-buffered cp.async; 72KB smem ->
// 2 CTAs/SM (epilogue of one CTA overlaps MMA of the other).
// s8 k32 fragment layout is byte-identical to e4m3 k32 / bf16 k16.
// ---------------------------------------------------------------------------
__global__ __launch_bounds__(256, 2)
void k_simgemm_sym(int Nn, int B) {
    extern __shared__ uint8_t smem[];
    uint8_t* As = smem;                      // 2 stages
    uint8_t* Bs = smem + 2 * ST_BYTES;       // 2 stages

    // decode lower-triangle tile (by >= bx)
    int idx = blockIdx.x;
    int by = (int)((sqrtf(8.0f * (float)idx + 1.0f) - 1.0f) * 0.5f);
    while ((by + 1) * (by + 2) / 2 <= idx) by++;
    while (by * (by + 1) / 2 > idx) by--;
    int bx = idx - by * (by + 1) / 2;
    const int r0 = by * TILE, c0 = bx * TILE;
    const bool diag = (by == bx);

    const int tid = threadIdx.x;
    const int wid = tid >> 5, lid = tid & 31;

    // chunk loader: 128 rows x 128 B per matrix = 1024 x 16B -> 4/thread each
    auto issue_chunk = [&](int ch) {
        #pragma unroll
        for (int q = 0; q < 4; q++) {
            int li  = tid + q * 256;            // 0..1023
            int row = li >> 3;                  // 0..127
            int seg = (li & 7) << 4;            // 0..112 bytes
            uint32_t dstA = smem_u32(&As[ch * ST_BYTES + row * CHKB + seg]);
            uint32_t dstB = smem_u32(&Bs[ch * ST_BYTES + row * CHKB + seg]);
            cp_async16(dstA, &g_znq[(size_t)(r0 + row) * D + ch * 128 + seg]);
            cp_async16(dstB, &g_znq[(size_t)(c0 + row) * D + ch * 128 + seg]);
        }
        CP_COMMIT();
    };

    issue_chunk(0);
    issue_chunk(1);

    const int warp_m = wid & 3;
    const int warp_n = wid >> 2;

    // per-lane ldmatrix base addresses (stage 0), byte offsets
    uint32_t aAddr[2];
    #pragma unroll
    for (int mf = 0; mf < 2; mf++) {
        int row = warp_m * 32 + mf * 16 + (lid & 15);
        int colb = (lid >> 4) << 4;             // 0 or 16
        aAddr[mf] = smem_u32(&As[row * CHKB + colb]);
    }
    uint32_t bAddr[4];
    #pragma unroll
    for (int nq = 0; nq < 4; nq++) {
        int row = warp_n * 64 + nq * 16 + ((lid >> 4) << 3) + (lid & 7);
        int colb = (lid & 8) << 1;              // 0 or 16
        bAddr[nq] = smem_u32(&Bs[row * CHKB + colb]);
    }

    int acc[2][8][4];
    #pragma unroll
    for (int i = 0; i < 2; i++)
        #pragma unroll
        for (int j = 0; j < 8; j++)
            #pragma unroll
            for (int e = 0; e < 4; e++) acc[i][j][e] = 0;

    #pragma unroll
    for (int ch = 0; ch < 2; ch++) {
        if (ch == 0) CP_WAIT(1); else CP_WAIT(0);
        __syncthreads();
        const uint32_t cb = (uint32_t)ch * ST_BYTES;
        #pragma unroll
        for (int ks = 0; ks < 4; ks++) {          // 4 k-steps of 32 per chunk
            const uint32_t kb = cb + ks * 32;
            uint32_t a[2][4], b[4][4];
            #pragma unroll
            for (int mf = 0; mf < 2; mf++)
                asm volatile("ldmatrix.sync.aligned.m8n8.x4.shared.b16 {%0,%1,%2,%3}, [%4];"
                             : "=r"(a[mf][0]), "=r"(a[mf][1]), "=r"(a[mf][2]), "=r"(a[mf][3])
                             : "r"(aAddr[mf] + kb));
            #pragma unroll
            for (int nq = 0; nq < 4; nq++)
                asm volatile("ldmatrix.sync.aligned.m8n8.x4.shared.b16 {%0,%1,%2,%3}, [%4];"
                             : "=r"(b[nq][0]), "=r"(b[nq][1]), "=r"(b[nq][2]), "=r"(b[nq][3])
                             : "r"(bAddr[nq] + kb));
            #pragma unroll
            for (int mf = 0; mf < 2; mf++)
                #pragma unroll
                for (int nf = 0; nf < 8; nf++) {
                    const int nq = nf >> 1, base = (nf & 1) * 2;
                    asm volatile(
                        "mma.sync.aligned.m16n8k32.row.col.s32.s8.s8.s32 "
                        "{%0,%1,%2,%3}, {%4,%5,%6,%7}, {%8,%9}, {%0,%1,%2,%3};"
                        : "+r"(acc[mf][nf][0]), "+r"(acc[mf][nf][1]),
                          "+r"(acc[mf][nf][2]), "+r"(acc[mf][nf][3])
                        : "r"(a[mf][0]), "r"(a[mf][1]), "r"(a[mf][2]), "r"(a[mf][3]),
                          "r"(b[nq][base]), "r"(b[nq][base + 1]));
                }
        }
        // no trailing __syncthreads: each buffer is filled once, never reused
    }

    // -----------------------------------------------------------------------
    // Epilogue. sim = 2*acc/127^2. Off-diag: exp into row sums AND column
    // sums (mirror tile). Diag: row sums only, mask c==r. One pos write
    // covers (r,c) and (c,r); pos pairs only in tiles with by == bx + B/TILE.
    // -----------------------------------------------------------------------
    const float SC = 2.0f / 16129.0f;   // 2 / 127^2
    const int qrow = lid >> 2, qcol = lid & 3;
    const bool has_pos = (by == bx + (B / TILE));
    float rs[4] = {0.f, 0.f, 0.f, 0.f};
    float cs[8][2];
    #pragma unroll
    for (int nf = 0; nf < 8; nf++) { cs[nf][0] = 0.f; cs[nf][1] = 0.f; }

    #pragma unroll
    for (int mf = 0; mf < 2; mf++) {
        #pragma unroll
        for (int sub = 0; sub < 2; sub++) {
            const int r = r0 + warp_m * 32 + mf * 16 + sub * 8 + qrow;
            const int partner = (r < B) ? (r + B) : (r - B);
            #pragma unroll
            for (int nf = 0; nf < 8; nf++) {
                #pragma unroll
                for (int e = 0; e < 2; e++) {
                    const int c = c0 + warp_n * 64 + nf * 8 + qcol * 2 + e;
                    const float sim = SC * (float)acc[mf][nf][sub * 2 + e];
                    float ex = fast_exp_nonpos(sim - 2.0f);
                    if (diag && c == r) ex = 0.0f;
                    rs[mf * 2 + sub] += ex;
                    if (!diag) cs[nf][e] += ex;
                    if (has_pos && c == partner) { g_pos[r] = sim; g_pos[c] = sim; }
                }
            }
        }
    }

    // row sums: reduce across qcol (lanes 1,2)
    #pragma unroll
    for (int i = 0; i < 4; i++) {
        rs[i] += __shfl_xor_sync(0xffffffffu, rs[i], 1);
        rs[i] += __shfl_xor_sync(0xffffffffu, rs[i], 2);
    }
    if (qcol == 0) {
        #pragma unroll
        for (int mf = 0; mf < 2; mf++)
            #pragma unroll
            for (int sub = 0; sub < 2; sub++) {
                const int r = r0 + warp_m * 32 + mf * 16 + sub * 8 + qrow;
                atomicAdd(&g_S[r], rs[mf * 2 + sub]);
            }
    }

    // col sums: reduce across qrow (lanes 4,8,16); lanes 0..3 write
    if (!diag) {
        #pragma unroll
        for (int nf = 0; nf < 8; nf++) {
            #pragma unroll
            for (int e = 0; e < 2; e++) {
                float v = cs[nf][e];
                v += __shfl_xor_sync(0xffffffffu, v, 4);
                v += __shfl_xor_sync(0xffffffffu, v, 8);
                v += __shfl_xor_sync(0xffffffffu, v, 16);
                if (lid < 4) {
                    const int c = c0 + warp_n * 64 + nf * 8 + qcol * 2 + e;
                    atomicAdd(&g_S[c], v);
                }
            }
        }
    }
}

// ---------------------------------------------------------------------------
// Kernel 3: loss = (1/N) * sum_i (2 + log(S_i) - pos_i)
// ---------------------------------------------------------------------------
__global__ void k_final(float* __restrict__ out, int Nn) {
    int t = threadIdx.x;
    float s = 0.0f;
    for (int i = t; i < Nn; i += 1024)
        s += 2.0f + logf(g_S[i]) - g_pos[i];
    #pragma unroll
    for (int o = 16; o > 0; o >>= 1) s += __shfl_xor_sync(0xffffffffu, s, o);
    __shared__ float ws[32];
    if ((t & 31) == 0) ws[t >> 5] = s;
    __syncthreads();
    if (t < 32) {
        float x = ws[t];
        #pragma unroll
        for (int o = 16; o > 0; o >>= 1) x += __shfl_xor_sync(0xffffffffu, x, o);
        if (t == 0) out[0] = x / (float)Nn;
    }
}

// ---------------------------------------------------------------------------
extern "C" void kernel_launch(void* const* d_in, const int* in_sizes, int n_in,
                              void* d_out, int out_size) {
    const float* zi = (const float*)d_in[0];
    const float* zj = (const float*)d_in[1];
    int B  = in_sizes[0] / D;   // 4096
    int Nn = 2 * B;             // 8192

    const int smem_bytes = 4 * ST_BYTES;   // 73728
    cudaFuncSetAttribute(k_simgemm_sym,
                         cudaFuncAttributeMaxDynamicSharedMemorySize, smem_bytes);

    k_normalize<<<Nn / 8, 256>>>(zi, zj, B);
    const int ntiles = Nn / TILE;                  // 64
    const int nblocks = ntiles * (ntiles + 1) / 2; // 2080
    k_simgemm_sym<<<nblocks, 256, smem_bytes>>>(Nn, B);
    k_final<<<1, 1024>>>((float*)d_out, Nn);
}